// round 13
// baseline (speedup 1.0000x reference)
#include <cuda_runtime.h>
#include <cuda_bf16.h>
#include <cuda_fp16.h>

#define HH 64
#define GRID_BLOCKS 2048
#define THREADS 128
#define BSTR 44   // words per (chunk,lane) fragment row; 44 mod 32 = 12 -> conflict-free .128

// fast tanh + first three derivatives via ex2.approx + rcp.approx
__device__ __forceinline__ void tanh_derivs(float x, float& f, float& f1, float& f2, float& f3) {
    float e, r;
    asm("ex2.approx.f32 %0, %1;" : "=f"(e) : "f"(x * 2.885390081777927f)); // 2*log2(e)
    asm("rcp.approx.f32 %0, %1;" : "=f"(r) : "f"(e + 1.0f));
    f  = fmaf(-2.0f, r, 1.0f);
    f1 = 1.0f - f * f;
    f2 = -2.0f * f * f1;
    f3 = -2.0f * (f1 * f1 + f * f2);
}

// pack two f32 into half2: first asm operand -> UPPER half
#define PACK_H2(d, hif, lof) \
    asm("cvt.rn.f16x2.f32 %0, %1, %2;" : "=r"(d) : "f"(hif), "f"(lof))

// f32 -> value exactly representable in f16 (round trip), for A-table build
__device__ __forceinline__ float h2f_round(float v) {
    float o;
    asm("{.reg .f16 t; cvt.rn.f16.f32 t, %1; cvt.f32.f16 %0, t;}" : "=f"(o) : "f"(v));
    return o;
}

// top-10-mantissa-bit truncation (f16-exact to within subnormal slop)
__device__ __forceinline__ float mask_hi(float v) {
    return __uint_as_float(__float_as_uint(v) & 0xFFFFE000u);
}

// mma.m16n8k16 f16 inputs, f32 accumulate
#define MMA16(C, A, b0, b1) \
    asm("mma.sync.aligned.m16n8k16.row.col.f32.f16.f16.f32 " \
        "{%0,%1,%2,%3},{%4,%5,%6,%7},{%8,%9},{%0,%1,%2,%3};" \
        : "+f"((C)[0]), "+f"((C)[1]), "+f"((C)[2]), "+f"((C)[3]) \
        : "r"((A).x), "r"((A).y), "r"((A).z), "r"((A).w), "r"(b0), "r"(b1))

// split B (va..vd), pack to (b0h,b1h,b0l,b1l), store one uint4 to the stage buffer
#define EMIT_STORE(c) do { \
    const float _ha = mask_hi(va), _hb = mask_hi(vb); \
    const float _hc = mask_hi(vc), _hd = mask_hi(vd); \
    uint4 _fr; \
    PACK_H2(_fr.x, _hb, _ha); \
    PACK_H2(_fr.y, _hd, _hc); \
    PACK_H2(_fr.z, vb - _hb, va - _ha); \
    PACK_H2(_fr.w, vd - _hd, vc - _hc); \
    *(uint4*)&dst[(c) * 4] = _fr; \
} while (0)

// Faa di Bruno: accumulate w3 * jet(tanh(z)) into acc9[0..8]
__device__ __forceinline__ void compose_scalar(const float* z, float w3, float* acc9) {
    float f, f1, f2, f3;
    tanh_derivs(z[0], f, f1, f2, f3);
    const float zp = z[1], zt = z[2], zpp = z[3], zpt = z[4], ztt = z[5];
    const float zppp = z[6], zppt = z[7], zptt = z[8], zttt = z[9];
    acc9[0] = fmaf(w3, f1 * zp, acc9[0]);
    acc9[1] = fmaf(w3, f1 * zt, acc9[1]);
    acc9[2] = fmaf(w3, fmaf(f2, zp * zp, f1 * zpp), acc9[2]);
    acc9[3] = fmaf(w3, fmaf(f2, zp * zt, f1 * zpt), acc9[3]);
    acc9[4] = fmaf(w3, fmaf(f2, zt * zt, f1 * ztt), acc9[4]);
    acc9[5] = fmaf(w3, f3 * zp * zp * zp + 3.0f * f2 * zp * zpp + f1 * zppp, acc9[5]);
    acc9[6] = fmaf(w3, f3 * zp * zp * zt + f2 * (zpp * zt + 2.0f * zp * zpt) + f1 * zppt, acc9[6]);
    acc9[7] = fmaf(w3, f3 * zp * zt * zt + f2 * (ztt * zp + 2.0f * zt * zpt) + f1 * zptt, acc9[7]);
    acc9[8] = fmaf(w3, f3 * zt * zt * zt + 3.0f * f2 * zt * ztt + f1 * zttt, acc9[8]);
}

__global__ __launch_bounds__(THREADS, 5) void pinn_flow_kernel(
    const float* __restrict__ phi, const float* __restrict__ theta,
    const float* __restrict__ radius, const float* __restrict__ hth,
    const float* __restrict__ hph, const float* __restrict__ brr,
    const float* __restrict__ W1, const float* __restrict__ b1,
    const float* __restrict__ W2, const float* __restrict__ b2,
    const float* __restrict__ W3, const float* __restrict__ b3,
    float* __restrict__ out, int n)
{
    // fp16 A-fragment tables (hi/lo), m16n8k16 layout; [kq][chunk][lane]
    __shared__ __align__(16) uint4 sAh[4][4][32];        // 8 KB
    __shared__ __align__(16) uint4 sAl[4][4][32];        // 8 KB
    // staged B fragments: [chunk][lane] -> 10 uint4 (hi0,hi1,lo0,lo1 per coeff)
    __shared__ __align__(16) unsigned sBf[4 * 32 * BSTR];// 22.5 KB
    __shared__ __align__(16) float sL1[HH][12];          // 3 KB
    __shared__ float sB2[HH];
    __shared__ float sW3[HH];
    __shared__ float sTred[4][8][9];                     // per-kq partial T-jets

    const int tid = threadIdx.x;

    for (int idx = tid; idx < 512; idx += THREADS) {
        const int kq    = idx >> 7;
        const int chunk = (idx >> 5) & 3;
        const int ln    = idx & 31;
        const int g = ln >> 2, t4 = ln & 3;
        const int kb = kq * 16;
        const int jA = chunk * 16 + 2 * t4;
        float v[8], h[8], l[8];
        v[0] = W2[(jA    ) * HH + kb + g];
        v[1] = W2[(jA + 1) * HH + kb + g];
        v[2] = W2[(jA    ) * HH + kb + g + 8];
        v[3] = W2[(jA + 1) * HH + kb + g + 8];
        v[4] = W2[(jA + 8) * HH + kb + g];
        v[5] = W2[(jA + 9) * HH + kb + g];
        v[6] = W2[(jA + 8) * HH + kb + g + 8];
        v[7] = W2[(jA + 9) * HH + kb + g + 8];
        #pragma unroll
        for (int q = 0; q < 8; ++q) { h[q] = h2f_round(v[q]); l[q] = v[q] - h[q]; }
        uint4 Ah4, Al4;
        PACK_H2(Ah4.x, h[1], h[0]);
        PACK_H2(Ah4.y, h[3], h[2]);
        PACK_H2(Ah4.z, h[5], h[4]);
        PACK_H2(Ah4.w, h[7], h[6]);
        PACK_H2(Al4.x, l[1], l[0]);
        PACK_H2(Al4.y, l[3], l[2]);
        PACK_H2(Al4.z, l[5], l[4]);
        PACK_H2(Al4.w, l[7], l[6]);
        sAh[kq][chunk][ln] = Ah4;
        sAl[kq][chunk][ln] = Al4;
    }
    if (tid < HH) {
        sB2[tid] = b2[tid];
        sW3[tid] = W3[tid];
        const float a = W1[tid];        // W1[0][j]
        const float b = W1[HH + tid];   // W1[1][j]
        sL1[tid][0] = a;       sL1[tid][1] = b;
        sL1[tid][2] = a * a;   sL1[tid][3] = a * b;     sL1[tid][4] = b * b;
        sL1[tid][5] = a * a * a; sL1[tid][6] = a * a * b;
        sL1[tid][7] = a * b * b; sL1[tid][8] = b * b * b;
        sL1[tid][9] = b1[tid];
        sL1[tid][10] = 0.0f; sL1[tid][11] = 0.0f;
    }
    __syncthreads();

    const int lane = tid & 31;
    const int w    = tid >> 5;    // warp = its kq AND its build-chunk
    const int gid  = lane >> 2;   // point column 0..7
    const int tig  = lane & 3;
    const int ntiles = (n + 7) >> 3;   // 8 points per block-tile

    for (int tile = blockIdx.x; tile < ntiles; tile += GRID_BLOCKS) {
        const int base = tile * 8;
        const int myp  = base + gid;
        const int mypL = (myp < n) ? myp : (n - 1);
        const float p = phi[mypL];
        const float t = theta[mypL];

        // ---- Build phase: warp w builds chunk w's B fragments, stores packed ----
        {
            const int jA = w * 16 + 2 * tig;
            const int jB = jA + 1;
            const int jC = jA + 8;
            const int jD = jA + 9;

            const float2 eA = *(const float2*)&sL1[jA][0];
            const float2 eB = *(const float2*)&sL1[jB][0];
            const float2 eC = *(const float2*)&sL1[jC][0];
            const float2 eD = *(const float2*)&sL1[jD][0];
            const float2 gA = *(const float2*)&sL1[jA][8];
            const float2 gB = *(const float2*)&sL1[jB][8];
            const float2 gC = *(const float2*)&sL1[jC][8];
            const float2 gD = *(const float2*)&sL1[jD][8];

            float f0a, f1a, f2a, f3a, f0b, f1b, f2b, f3b;
            float f0c, f1c, f2c, f3c, f0d, f1d, f2d, f3d;
            tanh_derivs(fmaf(eA.x, p, fmaf(eA.y, t, gA.y)), f0a, f1a, f2a, f3a);
            tanh_derivs(fmaf(eB.x, p, fmaf(eB.y, t, gB.y)), f0b, f1b, f2b, f3b);
            tanh_derivs(fmaf(eC.x, p, fmaf(eC.y, t, gC.y)), f0c, f1c, f2c, f3c);
            tanh_derivs(fmaf(eD.x, p, fmaf(eD.y, t, gD.y)), f0d, f1d, f2d, f3d);

            unsigned* dst = &sBf[(w * 32 + lane) * BSTR];
            float va, vb, vc, vd;

            va = f0a; vb = f0b; vc = f0c; vd = f0d;                              EMIT_STORE(0);
            va = f1a * eA.x; vb = f1b * eB.x; vc = f1c * eC.x; vd = f1d * eD.x;  EMIT_STORE(1);
            va = f1a * eA.y; vb = f1b * eB.y; vc = f1c * eC.y; vd = f1d * eD.y;  EMIT_STORE(2);
            {
                const float2 qA = *(const float2*)&sL1[jA][2];
                const float2 qB = *(const float2*)&sL1[jB][2];
                const float2 qC = *(const float2*)&sL1[jC][2];
                const float2 qD = *(const float2*)&sL1[jD][2];
                va = f2a * qA.x; vb = f2b * qB.x; vc = f2c * qC.x; vd = f2d * qD.x;  EMIT_STORE(3);
                va = f2a * qA.y; vb = f2b * qB.y; vc = f2c * qC.y; vd = f2d * qD.y;  EMIT_STORE(4);
            }
            {
                const float2 qA = *(const float2*)&sL1[jA][4];
                const float2 qB = *(const float2*)&sL1[jB][4];
                const float2 qC = *(const float2*)&sL1[jC][4];
                const float2 qD = *(const float2*)&sL1[jD][4];
                va = f2a * qA.x; vb = f2b * qB.x; vc = f2c * qC.x; vd = f2d * qD.x;  EMIT_STORE(5);
                va = f3a * qA.y; vb = f3b * qB.y; vc = f3c * qC.y; vd = f3d * qD.y;  EMIT_STORE(6);
            }
            {
                const float2 qA = *(const float2*)&sL1[jA][6];
                const float2 qB = *(const float2*)&sL1[jB][6];
                const float2 qC = *(const float2*)&sL1[jC][6];
                const float2 qD = *(const float2*)&sL1[jD][6];
                va = f3a * qA.x; vb = f3b * qB.x; vc = f3c * qC.x; vd = f3d * qD.x;  EMIT_STORE(7);
                va = f3a * qA.y; vb = f3b * qB.y; vc = f3c * qC.y; vd = f3d * qD.y;  EMIT_STORE(8);
            }
            va = f3a * gA.x; vb = f3b * gB.x; vc = f3c * gC.x; vd = f3d * gD.x;      EMIT_STORE(9);
        }
        __syncthreads();

        // ---- MMA phase: warp w = kq w; read staged fragments, accumulate C ----
        float C[10][4];
        #pragma unroll
        for (int c = 0; c < 10; ++c) {
            C[c][0] = 0.0f; C[c][1] = 0.0f; C[c][2] = 0.0f; C[c][3] = 0.0f;
        }

        #pragma unroll
        for (int ch = 0; ch < 4; ++ch) {
            const uint4 Ah = sAh[w][ch][lane];
            const uint4 Al = sAl[w][ch][lane];
            const unsigned* src = &sBf[(ch * 32 + lane) * BSTR];
            #pragma unroll
            for (int c = 0; c < 10; ++c) {
                const uint4 fr = *(const uint4*)&src[c * 4];
                MMA16(C[c], Ah, fr.x, fr.y);
                MMA16(C[c], Ah, fr.z, fr.w);
                MMA16(C[c], Al, fr.x, fr.y);
            }
        }

        // ---- Compose this warp's kq into partial T-jets; reduce over gid lanes ----
        float Tj[18];
        #pragma unroll
        for (int q = 0; q < 18; ++q) Tj[q] = 0.0f;
        #pragma unroll
        for (int e = 0; e < 4; ++e) {
            const int k = w * 16 + gid + ((e & 2) ? 8 : 0);
            float z[10];
            #pragma unroll
            for (int c = 0; c < 10; ++c) z[c] = C[c][e];
            z[0] += sB2[k];
            compose_scalar(z, sW3[k], &Tj[(e & 1) * 9]);
        }
        #pragma unroll
        for (int q = 0; q < 18; ++q) {
            float v = Tj[q];
            v += __shfl_xor_sync(0xffffffffu, v, 4);
            v += __shfl_xor_sync(0xffffffffu, v, 8);
            v += __shfl_xor_sync(0xffffffffu, v, 16);
            Tj[q] = v;
        }
        if (lane < 4) {
            #pragma unroll
            for (int sel = 0; sel < 2; ++sel)
                #pragma unroll
                for (int cc = 0; cc < 9; ++cc)
                    sTred[w][2 * lane + sel][cc] = Tj[sel * 9 + cc];
        }
        __syncthreads();

        // ---- Epilogue: threads 0..7 finish one point each ----
        if (tid < 8) {
            const int i = base + tid;
            if (i < n) {
                float T[9];
                #pragma unroll
                for (int cc = 0; cc < 9; ++cc)
                    T[cc] = sTred[0][tid][cc] + sTred[1][tid][cc]
                          + sTred[2][tid][cc] + sTred[3][tid][cc];
                const float Tp = T[0], Tt = T[1];
                const float Tpp = T[2], Tpt = T[3], Ttt = T[4];
                const float Tppp = T[5], Tppt = T[6], Tptt = T[7], Tttt = T[8];

                const float th = theta[i];
                float s, cn;
                sincosf(th, &s, &cn);
                const float r    = radius[i];
                const float invs = 1.0f / s;
                const float invr = 1.0f / r;

                const float ut = fmaf(Tp, invs, Tt);
                const float up = fmaf(Tp, invs, -Tt);

                const float u_th_t = -(Tpt + cn * Tt + s * Ttt);
                const float u_ph_p = fmaf(Tpp, invs, -Tpt);
                const float div = (u_th_t + u_ph_p) * invs * invr;

                const float c2s2 = cn * cn - s * s;
                const float u_th_tt = -(cn * Tpt + s * Tptt + 3.0f * s * cn * Ttt
                                        + c2s2 * Tt + s * s * Tttt);
                const float u_th_pp = -(fmaf(Tppp, invs, Tppt));
                const float u_ph_tt = cn * Tpt + s * Tptt - c2s2 * Tt
                                      - 3.0f * s * cn * Ttt - s * s * Tttt;
                const float u_ph_pp = fmaf(Tppp, invs, -Tppt);

                const float invr2  = invr * invr;
                const float invrs2 = invs * invs * invr2;
                const float lapt = fmaf(s * invr2, u_th_tt, u_th_pp * invrs2);
                const float lapp = fmaf(s * invr2, u_ph_tt, u_ph_pp * invrs2);
                const float comp = s * (lapt * lapt + lapp * lapp);
                const float sv   = -(ut * hth[i] + up * hph[i]) - brr[i] * div;
                const float tg   = div - ut * (s / cn) * invr;

                out[i]         = ut;
                out[n + i]     = up;
                out[2 * n + i] = div;
                out[3 * n + i] = sv;
                out[4 * n + i] = tg;
                out[5 * n + i] = comp;
            }
        }
        __syncthreads();   // protect sBf/sTred before next tile overwrites
    }
}

extern "C" void kernel_launch(void* const* d_in, const int* in_sizes, int n_in,
                              void* d_out, int out_size) {
    const float* phi    = (const float*)d_in[0];
    const float* theta  = (const float*)d_in[1];
    const float* radius = (const float*)d_in[2];
    const float* hth    = (const float*)d_in[3];
    const float* hph    = (const float*)d_in[4];
    const float* brr    = (const float*)d_in[5];
    const float* W1     = (const float*)d_in[6];
    const float* b1     = (const float*)d_in[7];
    const float* W2     = (const float*)d_in[8];
    const float* b2     = (const float*)d_in[9];
    const float* W3     = (const float*)d_in[10];
    const float* b3     = (const float*)d_in[11];
    float* out = (float*)d_out;
    const int n = in_sizes[0];

    pinn_flow_kernel<<<GRID_BLOCKS, THREADS>>>(
        phi, theta, radius, hth, hph, brr,
        W1, b1, W2, b2, W3, b3, out, n);
}

// round 16
// speedup vs baseline: 1.0623x; 1.0623x over previous
#include <cuda_runtime.h>
#include <cuda_bf16.h>
#include <cuda_fp16.h>

#define HH 64
#define GRID_BLOCKS 2048
#define THREADS 128
#define BSTR 44   // words/row: >=40 (10 uint4), mult of 4 (16B aligned), ==12 mod 32 -> conflict-free .128

// fp16 A-fragment tables (hi/lo) for W2^T, m16n8k16 layout; [kq][chunk][lane]
__device__ uint4 gAh[4][4][32];
__device__ uint4 gAl[4][4][32];

// fast tanh + first three derivatives via ex2.approx + rcp.approx
__device__ __forceinline__ void tanh_derivs(float x, float& f, float& f1, float& f2, float& f3) {
    float e, r;
    asm("ex2.approx.f32 %0, %1;" : "=f"(e) : "f"(x * 2.885390081777927f)); // 2*log2(e)
    asm("rcp.approx.f32 %0, %1;" : "=f"(r) : "f"(e + 1.0f));
    f  = fmaf(-2.0f, r, 1.0f);
    f1 = 1.0f - f * f;
    f2 = -2.0f * f * f1;
    f3 = -2.0f * (f1 * f1 + f * f2);
}

// pack two f32 into half2: first asm operand -> UPPER half
#define PACK_H2(d, hif, lof) \
    asm("cvt.rn.f16x2.f32 %0, %1, %2;" : "=r"(d) : "f"(hif), "f"(lof))

// f32 -> value exactly representable in f16 (round trip), for A-table build
__device__ __forceinline__ float h2f_round(float v) {
    float o;
    asm("{.reg .f16 t; cvt.rn.f16.f32 t, %1; cvt.f32.f16 %0, t;}" : "=f"(o) : "f"(v));
    return o;
}

// top-10-mantissa-bit truncation (f16-exact to within subnormal slop)
__device__ __forceinline__ float mask_hi(float v) {
    return __uint_as_float(__float_as_uint(v) & 0xFFFFE000u);
}

// mma.m16n8k16 f16 inputs, f32 accumulate
#define MMA16(C, A, b0, b1) \
    asm("mma.sync.aligned.m16n8k16.row.col.f32.f16.f16.f32 " \
        "{%0,%1,%2,%3},{%4,%5,%6,%7},{%8,%9},{%0,%1,%2,%3};" \
        : "+f"((C)[0]), "+f"((C)[1]), "+f"((C)[2]), "+f"((C)[3]) \
        : "r"((A).x), "r"((A).y), "r"((A).z), "r"((A).w), "r"(b0), "r"(b1))

// split B (va..vd), pack to (b0h,b1h,b0l,b1l), store one uint4 to the stage buffer
#define EMIT_STORE(c) do { \
    const float _ha = mask_hi(va), _hb = mask_hi(vb); \
    const float _hc = mask_hi(vc), _hd = mask_hi(vd); \
    uint4 _fr; \
    PACK_H2(_fr.x, _hb, _ha); \
    PACK_H2(_fr.y, _hd, _hc); \
    PACK_H2(_fr.z, vb - _hb, va - _ha); \
    PACK_H2(_fr.w, vd - _hd, vc - _hc); \
    *(uint4*)&dst[(c) * 4] = _fr; \
} while (0)

// Faa di Bruno: accumulate w3 * jet(tanh(z)) into acc9[0..8]
__device__ __forceinline__ void compose_scalar(const float* z, float w3, float* acc9) {
    float f, f1, f2, f3;
    tanh_derivs(z[0], f, f1, f2, f3);
    const float zp = z[1], zt = z[2], zpp = z[3], zpt = z[4], ztt = z[5];
    const float zppp = z[6], zppt = z[7], zptt = z[8], zttt = z[9];
    acc9[0] = fmaf(w3, f1 * zp, acc9[0]);
    acc9[1] = fmaf(w3, f1 * zt, acc9[1]);
    acc9[2] = fmaf(w3, fmaf(f2, zp * zp, f1 * zpp), acc9[2]);
    acc9[3] = fmaf(w3, fmaf(f2, zp * zt, f1 * zpt), acc9[3]);
    acc9[4] = fmaf(w3, fmaf(f2, zt * zt, f1 * ztt), acc9[4]);
    acc9[5] = fmaf(w3, f3 * zp * zp * zp + 3.0f * f2 * zp * zpp + f1 * zppp, acc9[5]);
    acc9[6] = fmaf(w3, f3 * zp * zp * zt + f2 * (zpp * zt + 2.0f * zp * zpt) + f1 * zppt, acc9[6]);
    acc9[7] = fmaf(w3, f3 * zp * zt * zt + f2 * (ztt * zp + 2.0f * zt * zpt) + f1 * zptt, acc9[7]);
    acc9[8] = fmaf(w3, f3 * zt * zt * zt + 3.0f * f2 * zt * ztt + f1 * zttt, acc9[8]);
}

__global__ void init_A_kernel(const float* __restrict__ W2) {
    const int idx = blockIdx.x * blockDim.x + threadIdx.x;
    if (idx >= 512) return;
    const int kq    = idx >> 7;
    const int chunk = (idx >> 5) & 3;
    const int ln    = idx & 31;
    const int g = ln >> 2, t4 = ln & 3;
    const int kb = kq * 16;
    const int jA = chunk * 16 + 2 * t4;
    float v[8], h[8], l[8];
    v[0] = W2[(jA    ) * HH + kb + g];
    v[1] = W2[(jA + 1) * HH + kb + g];
    v[2] = W2[(jA    ) * HH + kb + g + 8];
    v[3] = W2[(jA + 1) * HH + kb + g + 8];
    v[4] = W2[(jA + 8) * HH + kb + g];
    v[5] = W2[(jA + 9) * HH + kb + g];
    v[6] = W2[(jA + 8) * HH + kb + g + 8];
    v[7] = W2[(jA + 9) * HH + kb + g + 8];
    #pragma unroll
    for (int q = 0; q < 8; ++q) { h[q] = h2f_round(v[q]); l[q] = v[q] - h[q]; }
    uint4 Ah4, Al4;
    PACK_H2(Ah4.x, h[1], h[0]);
    PACK_H2(Ah4.y, h[3], h[2]);
    PACK_H2(Ah4.z, h[5], h[4]);
    PACK_H2(Ah4.w, h[7], h[6]);
    PACK_H2(Al4.x, l[1], l[0]);
    PACK_H2(Al4.y, l[3], l[2]);
    PACK_H2(Al4.z, l[5], l[4]);
    PACK_H2(Al4.w, l[7], l[6]);
    gAh[kq][chunk][ln] = Ah4;
    gAl[kq][chunk][ln] = Al4;
}

__global__ __launch_bounds__(THREADS, 6) void pinn_flow_kernel(
    const float* __restrict__ phi, const float* __restrict__ theta,
    const float* __restrict__ radius, const float* __restrict__ hth,
    const float* __restrict__ hph, const float* __restrict__ brr,
    const float* __restrict__ W1, const float* __restrict__ b1,
    const float* __restrict__ W2, const float* __restrict__ b2,
    const float* __restrict__ W3, const float* __restrict__ b3,
    float* __restrict__ out, int n)
{
    // staged B fragments: [chunk][lane] -> 10 uint4 (hi0,hi1,lo0,lo1 per coeff)
    __shared__ __align__(16) unsigned sBf[4 * 32 * BSTR];   // 22.5 KB
    __shared__ __align__(16) float sL1[HH][12];             // 3 KB
    __shared__ float sB2[HH];
    __shared__ float sW3[HH];
    __shared__ float sTred[4][8][9];                        // per-kq partial T-jets

    const int tid = threadIdx.x;

    if (tid < HH) {
        sB2[tid] = b2[tid];
        sW3[tid] = W3[tid];
        const float a = W1[tid];        // W1[0][j]
        const float b = W1[HH + tid];   // W1[1][j]
        sL1[tid][0] = a;       sL1[tid][1] = b;
        sL1[tid][2] = a * a;   sL1[tid][3] = a * b;     sL1[tid][4] = b * b;
        sL1[tid][5] = a * a * a; sL1[tid][6] = a * a * b;
        sL1[tid][7] = a * b * b; sL1[tid][8] = b * b * b;
        sL1[tid][9] = b1[tid];
        sL1[tid][10] = 0.0f; sL1[tid][11] = 0.0f;
    }
    __syncthreads();

    const int lane = tid & 31;
    const int w    = tid >> 5;    // warp = its kq AND its build-chunk
    const int gid  = lane >> 2;   // point column / k-row 0..7
    const int tig  = lane & 3;
    const int ntiles = (n + 7) >> 3;   // 8 points per block-tile

    for (int tile = blockIdx.x; tile < ntiles; tile += GRID_BLOCKS) {
        const int base = tile * 8;
        const int myp  = base + gid;
        const int mypL = (myp < n) ? myp : (n - 1);
        const float p = phi[mypL];
        const float t = theta[mypL];

        // ---- Build phase: warp w builds chunk w's B fragments, stores packed ----
        {
            const int jA = w * 16 + 2 * tig;
            const int jB = jA + 1;
            const int jC = jA + 8;
            const int jD = jA + 9;

            const float2 eA = *(const float2*)&sL1[jA][0];
            const float2 eB = *(const float2*)&sL1[jB][0];
            const float2 eC = *(const float2*)&sL1[jC][0];
            const float2 eD = *(const float2*)&sL1[jD][0];
            const float2 gA = *(const float2*)&sL1[jA][8];
            const float2 gB = *(const float2*)&sL1[jB][8];
            const float2 gC = *(const float2*)&sL1[jC][8];
            const float2 gD = *(const float2*)&sL1[jD][8];

            float f0a, f1a, f2a, f3a, f0b, f1b, f2b, f3b;
            float f0c, f1c, f2c, f3c, f0d, f1d, f2d, f3d;
            tanh_derivs(fmaf(eA.x, p, fmaf(eA.y, t, gA.y)), f0a, f1a, f2a, f3a);
            tanh_derivs(fmaf(eB.x, p, fmaf(eB.y, t, gB.y)), f0b, f1b, f2b, f3b);
            tanh_derivs(fmaf(eC.x, p, fmaf(eC.y, t, gC.y)), f0c, f1c, f2c, f3c);
            tanh_derivs(fmaf(eD.x, p, fmaf(eD.y, t, gD.y)), f0d, f1d, f2d, f3d);

            unsigned* dst = &sBf[(w * 32 + lane) * BSTR];
            float va, vb, vc, vd;

            va = f0a; vb = f0b; vc = f0c; vd = f0d;                              EMIT_STORE(0);
            va = f1a * eA.x; vb = f1b * eB.x; vc = f1c * eC.x; vd = f1d * eD.x;  EMIT_STORE(1);
            va = f1a * eA.y; vb = f1b * eB.y; vc = f1c * eC.y; vd = f1d * eD.y;  EMIT_STORE(2);
            {
                const float2 qA = *(const float2*)&sL1[jA][2];
                const float2 qB = *(const float2*)&sL1[jB][2];
                const float2 qC = *(const float2*)&sL1[jC][2];
                const float2 qD = *(const float2*)&sL1[jD][2];
                va = f2a * qA.x; vb = f2b * qB.x; vc = f2c * qC.x; vd = f2d * qD.x;  EMIT_STORE(3);
                va = f2a * qA.y; vb = f2b * qB.y; vc = f2c * qC.y; vd = f2d * qD.y;  EMIT_STORE(4);
            }
            {
                const float2 qA = *(const float2*)&sL1[jA][4];
                const float2 qB = *(const float2*)&sL1[jB][4];
                const float2 qC = *(const float2*)&sL1[jC][4];
                const float2 qD = *(const float2*)&sL1[jD][4];
                va = f2a * qA.x; vb = f2b * qB.x; vc = f2c * qC.x; vd = f2d * qD.x;  EMIT_STORE(5);
                va = f3a * qA.y; vb = f3b * qB.y; vc = f3c * qC.y; vd = f3d * qD.y;  EMIT_STORE(6);
            }
            {
                const float2 qA = *(const float2*)&sL1[jA][6];
                const float2 qB = *(const float2*)&sL1[jB][6];
                const float2 qC = *(const float2*)&sL1[jC][6];
                const float2 qD = *(const float2*)&sL1[jD][6];
                va = f3a * qA.x; vb = f3b * qB.x; vc = f3c * qC.x; vd = f3d * qD.x;  EMIT_STORE(7);
                va = f3a * qA.y; vb = f3b * qB.y; vc = f3c * qC.y; vd = f3d * qD.y;  EMIT_STORE(8);
            }
            va = f3a * gA.x; vb = f3b * gB.x; vc = f3c * gC.x; vd = f3d * gD.x;      EMIT_STORE(9);
        }
        __syncthreads();   // bar_A: staged fragments visible

        // ---- MMA phase: warp w = kq w; A-frags from L1-resident global table ----
        float C[10][4];
        #pragma unroll
        for (int c = 0; c < 10; ++c) {
            C[c][0] = 0.0f; C[c][1] = 0.0f; C[c][2] = 0.0f; C[c][3] = 0.0f;
        }

        #pragma unroll
        for (int ch = 0; ch < 4; ++ch) {
            const uint4 Ah = gAh[w][ch][lane];
            const uint4 Al = gAl[w][ch][lane];
            const unsigned* src = &sBf[(ch * 32 + lane) * BSTR];
            #pragma unroll
            for (int c = 0; c < 10; ++c) {
                const uint4 fr = *(const uint4*)&src[c * 4];
                MMA16(C[c], Ah, fr.x, fr.y);
                MMA16(C[c], Ah, fr.z, fr.w);
                MMA16(C[c], Al, fr.x, fr.y);
            }
        }

        // ---- Compose: two column passes, Tj[9] live ----
        {
            const int k0 = w * 16 + gid;
            float Tj[9];
            // pass 0: column sel 0 (fragment elems e=0 [k0] and e=2 [k0+8])
            #pragma unroll
            for (int q = 0; q < 9; ++q) Tj[q] = 0.0f;
            {
                float z[10];
                #pragma unroll
                for (int c = 0; c < 10; ++c) z[c] = C[c][0];
                z[0] += sB2[k0];
                compose_scalar(z, sW3[k0], Tj);
                #pragma unroll
                for (int c = 0; c < 10; ++c) z[c] = C[c][2];
                z[0] += sB2[k0 + 8];
                compose_scalar(z, sW3[k0 + 8], Tj);
            }
            #pragma unroll
            for (int q = 0; q < 9; ++q) {
                float v = Tj[q];
                v += __shfl_xor_sync(0xffffffffu, v, 4);
                v += __shfl_xor_sync(0xffffffffu, v, 8);
                v += __shfl_xor_sync(0xffffffffu, v, 16);
                Tj[q] = v;
            }
            if (lane < 4) {
                #pragma unroll
                for (int cc = 0; cc < 9; ++cc)
                    sTred[w][2 * lane][cc] = Tj[cc];
            }
            // pass 1: column sel 1 (e=1 [k0] and e=3 [k0+8])
            #pragma unroll
            for (int q = 0; q < 9; ++q) Tj[q] = 0.0f;
            {
                float z[10];
                #pragma unroll
                for (int c = 0; c < 10; ++c) z[c] = C[c][1];
                z[0] += sB2[k0];
                compose_scalar(z, sW3[k0], Tj);
                #pragma unroll
                for (int c = 0; c < 10; ++c) z[c] = C[c][3];
                z[0] += sB2[k0 + 8];
                compose_scalar(z, sW3[k0 + 8], Tj);
            }
            #pragma unroll
            for (int q = 0; q < 9; ++q) {
                float v = Tj[q];
                v += __shfl_xor_sync(0xffffffffu, v, 4);
                v += __shfl_xor_sync(0xffffffffu, v, 8);
                v += __shfl_xor_sync(0xffffffffu, v, 16);
                Tj[q] = v;
            }
            if (lane < 4) {
                #pragma unroll
                for (int cc = 0; cc < 9; ++cc)
                    sTred[w][2 * lane + 1][cc] = Tj[cc];
            }
        }
        __syncthreads();   // bar_B: sTred complete (also guards sBf reuse next tile)

        // ---- Epilogue: threads 0..7 finish one point each ----
        if (tid < 8) {
            const int i = base + tid;
            if (i < n) {
                float T[9];
                #pragma unroll
                for (int cc = 0; cc < 9; ++cc)
                    T[cc] = sTred[0][tid][cc] + sTred[1][tid][cc]
                          + sTred[2][tid][cc] + sTred[3][tid][cc];
                const float Tp = T[0], Tt = T[1];
                const float Tpp = T[2], Tpt = T[3], Ttt = T[4];
                const float Tppp = T[5], Tppt = T[6], Tptt = T[7], Tttt = T[8];

                const float th = theta[i];
                float s, cn;
                sincosf(th, &s, &cn);
                const float r    = radius[i];
                const float invs = 1.0f / s;
                const float invr = 1.0f / r;

                const float ut = fmaf(Tp, invs, Tt);
                const float up = fmaf(Tp, invs, -Tt);

                const float u_th_t = -(Tpt + cn * Tt + s * Ttt);
                const float u_ph_p = fmaf(Tpp, invs, -Tpt);
                const float div = (u_th_t + u_ph_p) * invs * invr;

                const float c2s2 = cn * cn - s * s;
                const float u_th_tt = -(cn * Tpt + s * Tptt + 3.0f * s * cn * Ttt
                                        + c2s2 * Tt + s * s * Tttt);
                const float u_th_pp = -(fmaf(Tppp, invs, Tppt));
                const float u_ph_tt = cn * Tpt + s * Tptt - c2s2 * Tt
                                      - 3.0f * s * cn * Ttt - s * s * Tttt;
                const float u_ph_pp = fmaf(Tppp, invs, -Tppt);

                const float invr2  = invr * invr;
                const float invrs2 = invs * invs * invr2;
                const float lapt = fmaf(s * invr2, u_th_tt, u_th_pp * invrs2);
                const float lapp = fmaf(s * invr2, u_ph_tt, u_ph_pp * invrs2);
                const float comp = s * (lapt * lapt + lapp * lapp);
                const float sv   = -(ut * hth[i] + up * hph[i]) - brr[i] * div;
                const float tg   = div - ut * (s / cn) * invr;

                out[i]         = ut;
                out[n + i]     = up;
                out[2 * n + i] = div;
                out[3 * n + i] = sv;
                out[4 * n + i] = tg;
                out[5 * n + i] = comp;
            }
        }
        // next tile's sBf writes are fenced by bar_A; sTred writes by bar_A as well
        // (compose happens after bar_A, epilogue readers passed bar_B then re-arrive at bar_A)
    }
}

extern "C" void kernel_launch(void* const* d_in, const int* in_sizes, int n_in,
                              void* d_out, int out_size) {
    const float* phi    = (const float*)d_in[0];
    const float* theta  = (const float*)d_in[1];
    const float* radius = (const float*)d_in[2];
    const float* hth    = (const float*)d_in[3];
    const float* hph    = (const float*)d_in[4];
    const float* brr    = (const float*)d_in[5];
    const float* W1     = (const float*)d_in[6];
    const float* b1     = (const float*)d_in[7];
    const float* W2     = (const float*)d_in[8];
    const float* b2     = (const float*)d_in[9];
    const float* W3     = (const float*)d_in[10];
    const float* b3     = (const float*)d_in[11];
    float* out = (float*)d_out;
    const int n = in_sizes[0];

    init_A_kernel<<<2, 256>>>(W2);
    pinn_flow_kernel<<<GRID_BLOCKS, THREADS>>>(
        phi, theta, radius, hth, hph, brr,
        W1, b1, W2, b2, W3, b3, out, n);
}

// round 17
// speedup vs baseline: 1.0780x; 1.0148x over previous
#include <cuda_runtime.h>
#include <cuda_bf16.h>
#include <cuda_fp16.h>

#define HH 64
#define GRID_BLOCKS 2048
#define THREADS 128
#define BSTR 44   // words/row: >=40 (10 uint4), mult of 4 (16B aligned), ==12 mod 32 -> conflict-free .128

// fp16 A-fragment tables (hi/lo) for W2^T, m16n8k16 layout; [kq][chunk][lane]
__device__ uint4 gAh[4][4][32];
__device__ uint4 gAl[4][4][32];

// fast tanh + first three derivatives via ex2.approx + rcp.approx
__device__ __forceinline__ void tanh_derivs(float x, float& f, float& f1, float& f2, float& f3) {
    float e, r;
    asm("ex2.approx.f32 %0, %1;" : "=f"(e) : "f"(x * 2.885390081777927f)); // 2*log2(e)
    asm("rcp.approx.f32 %0, %1;" : "=f"(r) : "f"(e + 1.0f));
    f  = fmaf(-2.0f, r, 1.0f);
    f1 = 1.0f - f * f;
    f2 = -2.0f * f * f1;
    f3 = -2.0f * (f1 * f1 + f * f2);
}

// pack two f32 into half2: first asm operand -> UPPER half
#define PACK_H2(d, hif, lof) \
    asm("cvt.rn.f16x2.f32 %0, %1, %2;" : "=r"(d) : "f"(hif), "f"(lof))

// f32 -> value exactly representable in f16 (round trip), for A-table build
__device__ __forceinline__ float h2f_round(float v) {
    float o;
    asm("{.reg .f16 t; cvt.rn.f16.f32 t, %1; cvt.f32.f16 %0, t;}" : "=f"(o) : "f"(v));
    return o;
}

// top-10-mantissa-bit truncation (f16-exact to within subnormal slop)
__device__ __forceinline__ float mask_hi(float v) {
    return __uint_as_float(__float_as_uint(v) & 0xFFFFE000u);
}

// mma.m16n8k16 f16 inputs, f32 accumulate
#define MMA16(C, A, b0, b1) \
    asm("mma.sync.aligned.m16n8k16.row.col.f32.f16.f16.f32 " \
        "{%0,%1,%2,%3},{%4,%5,%6,%7},{%8,%9},{%0,%1,%2,%3};" \
        : "+f"((C)[0]), "+f"((C)[1]), "+f"((C)[2]), "+f"((C)[3]) \
        : "r"((A).x), "r"((A).y), "r"((A).z), "r"((A).w), "r"(b0), "r"(b1))

// split B (va..vd), pack to (b0h,b1h,b0l,b1l), store one uint4 to the stage buffer
#define EMIT_STORE(c) do { \
    const float _ha = mask_hi(va), _hb = mask_hi(vb); \
    const float _hc = mask_hi(vc), _hd = mask_hi(vd); \
    uint4 _fr; \
    PACK_H2(_fr.x, _hb, _ha); \
    PACK_H2(_fr.y, _hd, _hc); \
    PACK_H2(_fr.z, vb - _hb, va - _ha); \
    PACK_H2(_fr.w, vd - _hd, vc - _hc); \
    *(uint4*)&dst[(c) * 4] = _fr; \
} while (0)

// Faa di Bruno: accumulate w3 * jet(tanh(z)) into acc9[0..8]
__device__ __forceinline__ void compose_scalar(const float* z, float w3, float* acc9) {
    float f, f1, f2, f3;
    tanh_derivs(z[0], f, f1, f2, f3);
    const float zp = z[1], zt = z[2], zpp = z[3], zpt = z[4], ztt = z[5];
    const float zppp = z[6], zppt = z[7], zptt = z[8], zttt = z[9];
    acc9[0] = fmaf(w3, f1 * zp, acc9[0]);
    acc9[1] = fmaf(w3, f1 * zt, acc9[1]);
    acc9[2] = fmaf(w3, fmaf(f2, zp * zp, f1 * zpp), acc9[2]);
    acc9[3] = fmaf(w3, fmaf(f2, zp * zt, f1 * zpt), acc9[3]);
    acc9[4] = fmaf(w3, fmaf(f2, zt * zt, f1 * ztt), acc9[4]);
    acc9[5] = fmaf(w3, f3 * zp * zp * zp + 3.0f * f2 * zp * zpp + f1 * zppp, acc9[5]);
    acc9[6] = fmaf(w3, f3 * zp * zp * zt + f2 * (zpp * zt + 2.0f * zp * zpt) + f1 * zppt, acc9[6]);
    acc9[7] = fmaf(w3, f3 * zp * zt * zt + f2 * (ztt * zp + 2.0f * zt * zpt) + f1 * zptt, acc9[7]);
    acc9[8] = fmaf(w3, f3 * zt * zt * zt + 3.0f * f2 * zt * ztt + f1 * zttt, acc9[8]);
}

__global__ void init_A_kernel(const float* __restrict__ W2) {
    const int idx = blockIdx.x * blockDim.x + threadIdx.x;
    if (idx >= 512) return;
    const int kq    = idx >> 7;
    const int chunk = (idx >> 5) & 3;
    const int ln    = idx & 31;
    const int g = ln >> 2, t4 = ln & 3;
    const int kb = kq * 16;
    const int jA = chunk * 16 + 2 * t4;
    float v[8], h[8], l[8];
    v[0] = W2[(jA    ) * HH + kb + g];
    v[1] = W2[(jA + 1) * HH + kb + g];
    v[2] = W2[(jA    ) * HH + kb + g + 8];
    v[3] = W2[(jA + 1) * HH + kb + g + 8];
    v[4] = W2[(jA + 8) * HH + kb + g];
    v[5] = W2[(jA + 9) * HH + kb + g];
    v[6] = W2[(jA + 8) * HH + kb + g + 8];
    v[7] = W2[(jA + 9) * HH + kb + g + 8];
    #pragma unroll
    for (int q = 0; q < 8; ++q) { h[q] = h2f_round(v[q]); l[q] = v[q] - h[q]; }
    uint4 Ah4, Al4;
    PACK_H2(Ah4.x, h[1], h[0]);
    PACK_H2(Ah4.y, h[3], h[2]);
    PACK_H2(Ah4.z, h[5], h[4]);
    PACK_H2(Ah4.w, h[7], h[6]);
    PACK_H2(Al4.x, l[1], l[0]);
    PACK_H2(Al4.y, l[3], l[2]);
    PACK_H2(Al4.z, l[5], l[4]);
    PACK_H2(Al4.w, l[7], l[6]);
    gAh[kq][chunk][ln] = Ah4;
    gAl[kq][chunk][ln] = Al4;
}

__global__ __launch_bounds__(THREADS, 6) void pinn_flow_kernel(
    const float* __restrict__ phi, const float* __restrict__ theta,
    const float* __restrict__ radius, const float* __restrict__ hth,
    const float* __restrict__ hph, const float* __restrict__ brr,
    const float* __restrict__ W1, const float* __restrict__ b1,
    const float* __restrict__ W2, const float* __restrict__ b2,
    const float* __restrict__ W3, const float* __restrict__ b3,
    float* __restrict__ out, int n)
{
    // staged B fragments: [chunk][lane] -> 10 uint4 (hi0,hi1,lo0,lo1 per coeff)
    __shared__ __align__(16) unsigned sBf[4 * 32 * BSTR];   // 22.5 KB
    __shared__ __align__(16) float4 sL14[HH];               // (a, b, b1, 0) per unit — 1 KB
    __shared__ float sB2[HH];
    __shared__ float sW3[HH];
    __shared__ float sTred[4][8][9];                        // per-kq partial T-jets

    const int tid = threadIdx.x;

    if (tid < HH) {
        sB2[tid] = b2[tid];
        sW3[tid] = W3[tid];
        sL14[tid] = make_float4(W1[tid], W1[HH + tid], b1[tid], 0.0f);
    }
    __syncthreads();

    const int lane = tid & 31;
    const int w    = tid >> 5;    // warp = its kq AND its build-chunk
    const int gid  = lane >> 2;   // point column / k-row 0..7
    const int tig  = lane & 3;
    const int ntiles = (n + 7) >> 3;   // 8 points per block-tile

    for (int tile = blockIdx.x; tile < ntiles; tile += GRID_BLOCKS) {
        const int base = tile * 8;
        const int myp  = base + gid;
        const int mypL = (myp < n) ? myp : (n - 1);
        const float p = phi[mypL];
        const float t = theta[mypL];

        // ---- Build phase: warp w builds chunk w's B fragments, stores packed ----
        {
            const int jA = w * 16 + 2 * tig;   // units jA, jA+1, jA+8, jA+9

            const float4 mA = sL14[jA];
            const float4 mB = sL14[jA + 1];
            const float4 mC = sL14[jA + 8];
            const float4 mD = sL14[jA + 9];

            float f0a, f1a, f2a, f3a, f0b, f1b, f2b, f3b;
            float f0c, f1c, f2c, f3c, f0d, f1d, f2d, f3d;
            tanh_derivs(fmaf(mA.x, p, fmaf(mA.y, t, mA.z)), f0a, f1a, f2a, f3a);
            tanh_derivs(fmaf(mB.x, p, fmaf(mB.y, t, mB.z)), f0b, f1b, f2b, f3b);
            tanh_derivs(fmaf(mC.x, p, fmaf(mC.y, t, mC.z)), f0c, f1c, f2c, f3c);
            tanh_derivs(fmaf(mD.x, p, fmaf(mD.y, t, mD.z)), f0d, f1d, f2d, f3d);

            unsigned* dst = &sBf[(w * 32 + lane) * BSTR];
            float va, vb, vc, vd;

            // c0: f
            va = f0a; vb = f0b; vc = f0c; vd = f0d;                              EMIT_STORE(0);
            // c1: f1*a ; c2: f1*b
            va = f1a * mA.x; vb = f1b * mB.x; vc = f1c * mC.x; vd = f1d * mD.x;  EMIT_STORE(1);
            va = f1a * mA.y; vb = f1b * mB.y; vc = f1c * mC.y; vd = f1d * mD.y;  EMIT_STORE(2);
            // c3: f2*aa ; c4: f2*ab ; c5: f2*bb
            {
                const float ta = f2a * mA.x, tb = f2b * mB.x, tc = f2c * mC.x, td = f2d * mD.x;
                va = ta * mA.x; vb = tb * mB.x; vc = tc * mC.x; vd = td * mD.x;  EMIT_STORE(3);
                va = ta * mA.y; vb = tb * mB.y; vc = tc * mC.y; vd = td * mD.y;  EMIT_STORE(4);
                va = (f2a * mA.y) * mA.y; vb = (f2b * mB.y) * mB.y;
                vc = (f2c * mC.y) * mC.y; vd = (f2d * mD.y) * mD.y;              EMIT_STORE(5);
            }
            // c6: f3*aaa ; c7: f3*aab ; c8: f3*abb ; c9: f3*bbb
            {
                const float ua = f3a * mA.x, ub = f3b * mB.x, uc = f3c * mC.x, ud = f3d * mD.x;
                const float wa = ua * mA.x, wb = ub * mB.x, wc = uc * mC.x, wd = ud * mD.x;
                va = wa * mA.x; vb = wb * mB.x; vc = wc * mC.x; vd = wd * mD.x;  EMIT_STORE(6);
                va = wa * mA.y; vb = wb * mB.y; vc = wc * mC.y; vd = wd * mD.y;  EMIT_STORE(7);
                va = (ua * mA.y) * mA.y; vb = (ub * mB.y) * mB.y;
                vc = (uc * mC.y) * mC.y; vd = (ud * mD.y) * mD.y;                EMIT_STORE(8);
                va = ((f3a * mA.y) * mA.y) * mA.y; vb = ((f3b * mB.y) * mB.y) * mB.y;
                vc = ((f3c * mC.y) * mC.y) * mC.y; vd = ((f3d * mD.y) * mD.y) * mD.y;  EMIT_STORE(9);
            }
        }
        __syncthreads();   // bar_A: staged fragments visible

        // ---- MMA phase: warp w = kq w; A-frags from L1-resident global table ----
        float C[10][4];
        #pragma unroll
        for (int c = 0; c < 10; ++c) {
            C[c][0] = 0.0f; C[c][1] = 0.0f; C[c][2] = 0.0f; C[c][3] = 0.0f;
        }

        #pragma unroll
        for (int ch = 0; ch < 4; ++ch) {
            const uint4 Ah = gAh[w][ch][lane];
            const uint4 Al = gAl[w][ch][lane];
            const unsigned* src = &sBf[(ch * 32 + lane) * BSTR];
            #pragma unroll
            for (int c = 0; c < 10; ++c) {
                const uint4 fr = *(const uint4*)&src[c * 4];
                MMA16(C[c], Ah, fr.x, fr.y);
                MMA16(C[c], Ah, fr.z, fr.w);
                MMA16(C[c], Al, fr.x, fr.y);
            }
        }

        // ---- Compose: two column passes, Tj[9] live ----
        {
            const int k0 = w * 16 + gid;
            float Tj[9];
            // pass 0: column sel 0 (fragment elems e=0 [k0] and e=2 [k0+8])
            #pragma unroll
            for (int q = 0; q < 9; ++q) Tj[q] = 0.0f;
            {
                float z[10];
                #pragma unroll
                for (int c = 0; c < 10; ++c) z[c] = C[c][0];
                z[0] += sB2[k0];
                compose_scalar(z, sW3[k0], Tj);
                #pragma unroll
                for (int c = 0; c < 10; ++c) z[c] = C[c][2];
                z[0] += sB2[k0 + 8];
                compose_scalar(z, sW3[k0 + 8], Tj);
            }
            #pragma unroll
            for (int q = 0; q < 9; ++q) {
                float v = Tj[q];
                v += __shfl_xor_sync(0xffffffffu, v, 4);
                v += __shfl_xor_sync(0xffffffffu, v, 8);
                v += __shfl_xor_sync(0xffffffffu, v, 16);
                Tj[q] = v;
            }
            if (lane < 4) {
                #pragma unroll
                for (int cc = 0; cc < 9; ++cc)
                    sTred[w][2 * lane][cc] = Tj[cc];
            }
            // pass 1: column sel 1 (e=1 [k0] and e=3 [k0+8])
            #pragma unroll
            for (int q = 0; q < 9; ++q) Tj[q] = 0.0f;
            {
                float z[10];
                #pragma unroll
                for (int c = 0; c < 10; ++c) z[c] = C[c][1];
                z[0] += sB2[k0];
                compose_scalar(z, sW3[k0], Tj);
                #pragma unroll
                for (int c = 0; c < 10; ++c) z[c] = C[c][3];
                z[0] += sB2[k0 + 8];
                compose_scalar(z, sW3[k0 + 8], Tj);
            }
            #pragma unroll
            for (int q = 0; q < 9; ++q) {
                float v = Tj[q];
                v += __shfl_xor_sync(0xffffffffu, v, 4);
                v += __shfl_xor_sync(0xffffffffu, v, 8);
                v += __shfl_xor_sync(0xffffffffu, v, 16);
                Tj[q] = v;
            }
            if (lane < 4) {
                #pragma unroll
                for (int cc = 0; cc < 9; ++cc)
                    sTred[w][2 * lane + 1][cc] = Tj[cc];
            }
        }
        __syncthreads();   // bar_B: sTred complete (also guards sBf reuse next tile)

        // ---- Epilogue: threads 0..7 finish one point each ----
        if (tid < 8) {
            const int i = base + tid;
            if (i < n) {
                float T[9];
                #pragma unroll
                for (int cc = 0; cc < 9; ++cc)
                    T[cc] = sTred[0][tid][cc] + sTred[1][tid][cc]
                          + sTred[2][tid][cc] + sTred[3][tid][cc];
                const float Tp = T[0], Tt = T[1];
                const float Tpp = T[2], Tpt = T[3], Ttt = T[4];
                const float Tppp = T[5], Tppt = T[6], Tptt = T[7], Tttt = T[8];

                const float th = theta[i];
                float s, cn;
                sincosf(th, &s, &cn);
                const float r    = radius[i];
                const float invs = 1.0f / s;
                const float invr = 1.0f / r;

                const float ut = fmaf(Tp, invs, Tt);
                const float up = fmaf(Tp, invs, -Tt);

                const float u_th_t = -(Tpt + cn * Tt + s * Ttt);
                const float u_ph_p = fmaf(Tpp, invs, -Tpt);
                const float div = (u_th_t + u_ph_p) * invs * invr;

                const float c2s2 = cn * cn - s * s;
                const float u_th_tt = -(cn * Tpt + s * Tptt + 3.0f * s * cn * Ttt
                                        + c2s2 * Tt + s * s * Tttt);
                const float u_th_pp = -(fmaf(Tppp, invs, Tppt));
                const float u_ph_tt = cn * Tpt + s * Tptt - c2s2 * Tt
                                      - 3.0f * s * cn * Ttt - s * s * Tttt;
                const float u_ph_pp = fmaf(Tppp, invs, -Tppt);

                const float invr2  = invr * invr;
                const float invrs2 = invs * invs * invr2;
                const float lapt = fmaf(s * invr2, u_th_tt, u_th_pp * invrs2);
                const float lapp = fmaf(s * invr2, u_ph_tt, u_ph_pp * invrs2);
                const float comp = s * (lapt * lapt + lapp * lapp);
                const float sv   = -(ut * hth[i] + up * hph[i]) - brr[i] * div;
                const float tg   = div - ut * (s / cn) * invr;

                out[i]         = ut;
                out[n + i]     = up;
                out[2 * n + i] = div;
                out[3 * n + i] = sv;
                out[4 * n + i] = tg;
                out[5 * n + i] = comp;
            }
        }
    }
}

extern "C" void kernel_launch(void* const* d_in, const int* in_sizes, int n_in,
                              void* d_out, int out_size) {
    const float* phi    = (const float*)d_in[0];
    const float* theta  = (const float*)d_in[1];
    const float* radius = (const float*)d_in[2];
    const float* hth    = (const float*)d_in[3];
    const float* hph    = (const float*)d_in[4];
    const float* brr    = (const float*)d_in[5];
    const float* W1     = (const float*)d_in[6];
    const float* b1     = (const float*)d_in[7];
    const float* W2     = (const float*)d_in[8];
    const float* b2     = (const float*)d_in[9];
    const float* W3     = (const float*)d_in[10];
    const float* b3     = (const float*)d_in[11];
    float* out = (float*)d_out;
    const int n = in_sizes[0];

    init_A_kernel<<<2, 256>>>(W2);
    pinn_flow_kernel<<<GRID_BLOCKS, THREADS>>>(
        phi, theta, radius, hth, hph, brr,
        W1, b1, W2, b2, W3, b3, out, n);
}